// round 13
// baseline (speedup 1.0000x reference)
#include <cuda_runtime.h>
#include <cstdint>

// Problem constants
#define B_ROWS    1024
#define IN_FEAT   76800
#define IN_G      19200     // IN_FEAT/4 (float4 / int8x4 groups)
#define OUT_FEAT  10
#define W_ELEMS   (OUT_FEAT * IN_FEAT)   // 768000
#define W_G       (OUT_FEAT * IN_G)      // 192000 packed groups

// quant kernel: one block per row, occ=1 (smem-forced) -> L2 reuse window 45MB
#define QT        960
#define QK        20                     // 20*960 = 19200
#define QUANT_SMEM (120 * 1024)          // dummy size forcing 1 block/SM

// gemv kernel (int8 input): 10 slices x 29 rowblocks = 290 CTAs, 480 thr, 2/SM
#define NSLICE    10
#define SLICE_G   (IN_G / NSLICE)        // 1920 groups
#define GGT       480                    // threads; 4 consecutive groups/thread
#define ROWBLK    29
#define GEMV_SMEM (OUT_FEAT * GGT * 16)  // 76800 B weight quads

// wsum reduction
#define WSUM_BLOCKS 125
#define WSUM_THREADS 256

// ---------------- device scratch (static, allocation-free) ----------------
__device__ float    g_wpart[WSUM_BLOCKS];
__device__ float    g_wscale;               // 1/clip(mean|W|,eps)
__device__ float    g_winv;                 // clip(mean|W|,eps)
__device__ float    g_rowscale[B_ROWS];     // 127/clip(rowmax,eps)
__device__ __align__(16) unsigned g_tw[W_G];           // ternary weights, int8x4, [o][g]
__device__ __align__(16) unsigned g_q[B_ROWS * IN_G];  // quantized activations, int8x4
__device__ int      g_dot[B_ROWS * OUT_FEAT];

// ---------------- kernel 1: sum |W| ----------------
__global__ void k_wsum(const float4* __restrict__ w4) {
    float s = 0.f;
    int idx = blockIdx.x * WSUM_THREADS + threadIdx.x;
    #pragma unroll
    for (int k = 0; k < 6; k++) {   // 125*256*6 = 192000 exactly
        float4 v = w4[idx + k * WSUM_BLOCKS * WSUM_THREADS];
        s += fabsf(v.x) + fabsf(v.y) + fabsf(v.z) + fabsf(v.w);
    }
    #pragma unroll
    for (int d = 16; d; d >>= 1) s += __shfl_down_sync(0xffffffffu, s, d);
    __shared__ float red[8];
    int warp = threadIdx.x >> 5, lane = threadIdx.x & 31;
    if (lane == 0) red[warp] = s;
    __syncthreads();
    if (threadIdx.x < 8) {
        float v = red[threadIdx.x];
        #pragma unroll
        for (int d = 4; d; d >>= 1) v += __shfl_down_sync(0xffu, v, d);
        if (threadIdx.x == 0) g_wpart[blockIdx.x] = v;
    }
}

// ---------------- kernel 2: finalize wscale ----------------
__global__ void k_wscale(void) {
    float s = (threadIdx.x < WSUM_BLOCKS) ? g_wpart[threadIdx.x] : 0.f;
    #pragma unroll
    for (int d = 16; d; d >>= 1) s += __shfl_down_sync(0xffffffffu, s, d);
    __shared__ float red[4];
    int warp = threadIdx.x >> 5, lane = threadIdx.x & 31;
    if (lane == 0) red[warp] = s;
    __syncthreads();
    if (threadIdx.x == 0) {
        float total = red[0] + red[1] + red[2] + red[3];
        float mean = fmaxf(total / (float)W_ELEMS, 1e-5f);
        g_winv = mean;
        g_wscale = 1.f / mean;
    }
}

// ---------------- kernel 3: ternarize W into packed int8x4 ----------------
__global__ void k_ternary(const float4* __restrict__ w4) {
    int i = blockIdx.x * 256 + threadIdx.x;   // grid 750*256 = 192000
    float ws = g_wscale;
    float4 v = w4[i];
    int t0 = (int)fminf(1.f, fmaxf(-1.f, rintf(v.x * ws)));
    int t1 = (int)fminf(1.f, fmaxf(-1.f, rintf(v.y * ws)));
    int t2 = (int)fminf(1.f, fmaxf(-1.f, rintf(v.z * ws)));
    int t3 = (int)fminf(1.f, fmaxf(-1.f, rintf(v.w * ws)));
    g_tw[i] = (unsigned)((t0 & 0xFF) | ((t1 & 0xFF) << 8) | ((t2 & 0xFF) << 16) | (t3 << 24));
}

// FMA magic-number quantize: round-to-nearest-even of x*as in one FFMA.
// (validated: rel_err 5.6e-5, well under 1e-3)
__device__ __forceinline__ unsigned quant_pack(float4 v, float as) {
    float f0 = __fmaf_rn(v.x, as, 12582912.f);   // 1.5*2^23
    float f1 = __fmaf_rn(v.y, as, 12582912.f);
    float f2 = __fmaf_rn(v.z, as, 12582912.f);
    float f3 = __fmaf_rn(v.w, as, 12582912.f);
    unsigned p01 = __byte_perm(__float_as_uint(f0), __float_as_uint(f1), 0x0040);
    unsigned p23 = __byte_perm(__float_as_uint(f2), __float_as_uint(f3), 0x0040);
    return __byte_perm(p01, p23, 0x5410);
}

// ---------------- kernel 4: absmax + quantize + int8 write, occ=1 ----------------
// One 960-thr block per row; 120KB dummy dynamic smem forces 1 block/SM, so the
// pass-2 re-read window is 148 rows x 307KB = 45MB + 11MB writes << L2. Pass 2
// therefore reads from L2, not DRAM. Also zeroes g_dot for this row.
__global__ void __launch_bounds__(QT) k_quant(const float4* __restrict__ x4) {
    extern __shared__ float red[];   // [0..29] warp maxima, [32] broadcast scale
    const int row = blockIdx.x;
    const int tid = threadIdx.x;
    if (tid < OUT_FEAT) g_dot[row * OUT_FEAT + tid] = 0;

    const float4* xr = x4 + (size_t)row * IN_G;

    // pass 1: row absmax (DRAM-bound, high MLP)
    float m = 0.f;
    #pragma unroll 5
    for (int k = 0; k < QK; k++) {
        float4 v = xr[tid + k * QT];
        m = fmaxf(m, fmaxf(fmaxf(fabsf(v.x), fabsf(v.y)),
                           fmaxf(fabsf(v.z), fabsf(v.w))));
    }
    #pragma unroll
    for (int d = 16; d; d >>= 1) m = fmaxf(m, __shfl_down_sync(0xffffffffu, m, d));
    int warp = tid >> 5, lane = tid & 31;
    if (lane == 0) red[warp] = m;
    __syncthreads();
    if (tid < 32) {
        float v = (tid < QT / 32) ? red[tid] : 0.f;
        #pragma unroll
        for (int d = 16; d; d >>= 1) v = fmaxf(v, __shfl_down_sync(0xffffffffu, v, d));
        if (tid == 0) {
            float asc = 127.f / fmaxf(v, 1e-5f);
            red[32] = asc;
            g_rowscale[row] = asc;
        }
    }
    __syncthreads();
    const float as = red[32];

    // pass 2: re-read (L2 hits by construction), quantize, write packed int8
    unsigned* qr = g_q + (size_t)row * IN_G;
    #pragma unroll 5
    for (int k = 0; k < QK; k++)
        qr[tid + k * QT] = quant_pack(xr[tid + k * QT], as);
}

// ---------------- kernel 5: int8 ternary GEMV, triple-batched ----------------
// Reads packed int8 activations: ONE LDG.128 per row per thread (4 consecutive
// groups). Descending rows harvest k_quant's freshest L2-resident output.
// 290 CTAs (2/SM), regs ~61 < 68 cap. REDUX + exact integer atomics; no syncs.
__global__ void __launch_bounds__(GGT, 2) k_gemv(void) {
    extern __shared__ uint4 swq[];   // [10][GGT] weight quads

    const int s = blockIdx.x;
    const int rb = blockIdx.y;
    const int tid = threadIdx.x;
    const int lane = tid & 31;
    const int gbase = s * SLICE_G;

    // one-time weight staging: 4 consecutive groups per thread per output
    #pragma unroll
    for (int o = 0; o < OUT_FEAT; o++)
        swq[o * GGT + tid] = *(const uint4*)(g_tw + o * IN_G + gbase + 4 * tid);
    __syncthreads();

    const unsigned* qb = g_q + gbase + 4 * tid;   // thread-fixed base

    int r0 = B_ROWS - 1 - rb;              // descending
    while (r0 >= 0) {
        const int r1 = r0 - ROWBLK;
        const int r2 = r0 - 2 * ROWBLK;
        const int r1c = (r1 >= 0) ? r1 : r0;   // tail: dup row, skip its atomic
        const int r2c = (r2 >= 0) ? r2 : r0;

        // 3 LDG.128 up-front
        const uint4 q0 = *(const uint4*)(qb + (size_t)r0  * IN_G);
        const uint4 q1 = *(const uint4*)(qb + (size_t)r1c * IN_G);
        const uint4 q2 = *(const uint4*)(qb + (size_t)r2c * IN_G);

        int acc0[OUT_FEAT], acc1[OUT_FEAT], acc2[OUT_FEAT];
        #pragma unroll
        for (int o = 0; o < OUT_FEAT; o++) {
            const uint4 w = swq[o * GGT + tid];
            int a0 = __dp4a((int)q0.x, (int)w.x, 0);
            int a1 = __dp4a((int)q1.x, (int)w.x, 0);
            int a2 = __dp4a((int)q2.x, (int)w.x, 0);
            a0 = __dp4a((int)q0.y, (int)w.y, a0);
            a1 = __dp4a((int)q1.y, (int)w.y, a1);
            a2 = __dp4a((int)q2.y, (int)w.y, a2);
            a0 = __dp4a((int)q0.z, (int)w.z, a0);
            a1 = __dp4a((int)q1.z, (int)w.z, a1);
            a2 = __dp4a((int)q2.z, (int)w.z, a2);
            acc0[o] = __dp4a((int)q0.w, (int)w.w, a0);
            acc1[o] = __dp4a((int)q1.w, (int)w.w, a1);
            acc2[o] = __dp4a((int)q2.w, (int)w.w, a2);
        }

        #pragma unroll
        for (int o = 0; o < OUT_FEAT; o++) {
            acc0[o] = __reduce_add_sync(0xffffffffu, acc0[o]);
            acc1[o] = __reduce_add_sync(0xffffffffu, acc1[o]);
            acc2[o] = __reduce_add_sync(0xffffffffu, acc2[o]);
        }
        if (lane == 0) {
            int* d0 = g_dot + r0 * OUT_FEAT;
            #pragma unroll
            for (int o = 0; o < OUT_FEAT; o++) atomicAdd(d0 + o, acc0[o]);
            if (r1 >= 0) {
                int* d1 = g_dot + r1 * OUT_FEAT;
                #pragma unroll
                for (int o = 0; o < OUT_FEAT; o++) atomicAdd(d1 + o, acc1[o]);
            }
            if (r2 >= 0) {
                int* d2 = g_dot + r2 * OUT_FEAT;
                #pragma unroll
                for (int o = 0; o < OUT_FEAT; o++) atomicAdd(d2 + o, acc2[o]);
            }
        }
        r0 -= 3 * ROWBLK;
    }
}

// ---------------- kernel 6: scale, bias, softmax ----------------
__global__ void k_finish(const float* __restrict__ bias, float* __restrict__ out) {
    int row = blockIdx.x * 128 + threadIdx.x;   // grid 8 x 128
    float inv_as = 1.f / g_rowscale[row];
    float coef = inv_as * g_winv;
    const int* dp = g_dot + row * OUT_FEAT;
    float logit[OUT_FEAT];
    float m = -3.4e38f;
    #pragma unroll
    for (int o = 0; o < OUT_FEAT; o++) {
        logit[o] = coef * (float)dp[o] + bias[o];
        m = fmaxf(m, logit[o]);
    }
    float ssum = 0.f;
    #pragma unroll
    for (int o = 0; o < OUT_FEAT; o++) { logit[o] = expf(logit[o] - m); ssum += logit[o]; }
    float inv_s = 1.f / ssum;
    #pragma unroll
    for (int o = 0; o < OUT_FEAT; o++) out[row * OUT_FEAT + o] = logit[o] * inv_s;
}

// ---------------- launch (fork/join: weight chain overlaps k_quant) ----------------
extern "C" void kernel_launch(void* const* d_in, const int* in_sizes, int n_in,
                              void* d_out, int out_size) {
    const float4* x4 = (const float4*)d_in[0];   // [1024,3,160,160] fp32
    const float4* w4 = (const float4*)d_in[1];   // [10,76800] fp32
    const float*  b  = (const float*)d_in[2];    // [10]
    float* out = (float*)d_out;

    static cudaStream_t s_side = nullptr;
    static cudaEvent_t ev_fork = nullptr, ev_join = nullptr;
    static int init_done = 0;
    if (!init_done) {
        cudaStreamCreateWithFlags(&s_side, cudaStreamNonBlocking);
        cudaEventCreateWithFlags(&ev_fork, cudaEventDisableTiming);
        cudaEventCreateWithFlags(&ev_join, cudaEventDisableTiming);
        cudaFuncSetAttribute(k_quant, cudaFuncAttributeMaxDynamicSharedMemorySize, QUANT_SMEM);
        cudaFuncSetAttribute(k_gemv, cudaFuncAttributeMaxDynamicSharedMemorySize, GEMV_SMEM);
        init_done = 1;
    }

    // fork: weight-prep chain on side stream, concurrent with k_quant
    cudaEventRecord(ev_fork, 0);
    cudaStreamWaitEvent(s_side, ev_fork, 0);
    k_wsum<<<WSUM_BLOCKS, WSUM_THREADS, 0, s_side>>>(w4);
    k_wscale<<<1, 128, 0, s_side>>>();
    k_ternary<<<W_G / 256, 256, 0, s_side>>>(w4);
    cudaEventRecord(ev_join, s_side);

    k_quant<<<B_ROWS, QT, QUANT_SMEM>>>(x4);      // absmax + int8 write (~65us)

    cudaStreamWaitEvent(0, ev_join, 0);
    dim3 ggrid(NSLICE, ROWBLK);
    k_gemv<<<ggrid, GGT, GEMV_SMEM>>>();          // int8 GEMV (~15-20us)
    k_finish<<<B_ROWS / 128, 128>>>(b, out);
}

// round 15
// speedup vs baseline: 1.1746x; 1.1746x over previous
#include <cuda_runtime.h>
#include <cstdint>

// Problem constants
#define B_ROWS    1024
#define IN_FEAT   76800
#define IN_G      19200     // IN_FEAT/4 (float4 / int8x4 groups)
#define OUT_FEAT  10
#define W_ELEMS   (OUT_FEAT * IN_FEAT)   // 768000
#define W_G       (OUT_FEAT * IN_G)      // 192000 packed groups

// rowmax kernel (proven config, at DRAM roofline)
#define QT        768
#define QK        25                     // 25*768 = 19200

// gemv kernel: 10 slices x 29 rowblocks = 290 CTAs (one wave at 2/SM), 384 thr
#define NSLICE    10
#define SLICE_G   (IN_G / NSLICE)        // 1920 groups
#define GT        384
#define GPT       (SLICE_G / GT)         // 5 k-steps/thread
#define ROWBLK    29
#define SWQ_WORDS (OUT_FEAT * GT * 4)
#define GEMV_SMEM ((SWQ_WORDS + OUT_FEAT * GT) * 4)   // 76800 B

// wsum reduction
#define WSUM_BLOCKS 125
#define WSUM_THREADS 256

// ---------------- device scratch (static, allocation-free) ----------------
__device__ float    g_wpart[WSUM_BLOCKS];
__device__ float    g_wscale;               // 1/clip(mean|W|,eps)
__device__ float    g_winv;                 // clip(mean|W|,eps)
__device__ float    g_rowscale[B_ROWS];     // 127/clip(rowmax,eps)
__device__ unsigned g_tw[W_G];              // ternary weights, packed int8x4, [o][g]
__device__ int      g_dot[B_ROWS * OUT_FEAT];

// ---------------- kernel 1: sum |W| ----------------
__global__ void k_wsum(const float4* __restrict__ w4) {
    float s = 0.f;
    int idx = blockIdx.x * WSUM_THREADS + threadIdx.x;
    #pragma unroll
    for (int k = 0; k < 6; k++) {   // 125*256*6 = 192000 exactly
        float4 v = w4[idx + k * WSUM_BLOCKS * WSUM_THREADS];
        s += fabsf(v.x) + fabsf(v.y) + fabsf(v.z) + fabsf(v.w);
    }
    #pragma unroll
    for (int d = 16; d; d >>= 1) s += __shfl_down_sync(0xffffffffu, s, d);
    __shared__ float red[8];
    int warp = threadIdx.x >> 5, lane = threadIdx.x & 31;
    if (lane == 0) red[warp] = s;
    __syncthreads();
    if (threadIdx.x < 8) {
        float v = red[threadIdx.x];
        #pragma unroll
        for (int d = 4; d; d >>= 1) v += __shfl_down_sync(0xffu, v, d);
        if (threadIdx.x == 0) g_wpart[blockIdx.x] = v;
    }
}

// ---------------- kernel 2: finalize wscale ----------------
__global__ void k_wscale(void) {
    float s = (threadIdx.x < WSUM_BLOCKS) ? g_wpart[threadIdx.x] : 0.f;
    #pragma unroll
    for (int d = 16; d; d >>= 1) s += __shfl_down_sync(0xffffffffu, s, d);
    __shared__ float red[4];
    int warp = threadIdx.x >> 5, lane = threadIdx.x & 31;
    if (lane == 0) red[warp] = s;
    __syncthreads();
    if (threadIdx.x == 0) {
        float total = red[0] + red[1] + red[2] + red[3];
        float mean = fmaxf(total / (float)W_ELEMS, 1e-5f);
        g_winv = mean;
        g_wscale = 1.f / mean;
    }
}

// ---------------- kernel 3: ternarize W into packed int8x4 ----------------
__global__ void k_ternary(const float4* __restrict__ w4) {
    int i = blockIdx.x * 256 + threadIdx.x;   // grid 750*256 = 192000
    float ws = g_wscale;
    float4 v = w4[i];
    int t0 = (int)fminf(1.f, fmaxf(-1.f, rintf(v.x * ws)));
    int t1 = (int)fminf(1.f, fmaxf(-1.f, rintf(v.y * ws)));
    int t2 = (int)fminf(1.f, fmaxf(-1.f, rintf(v.z * ws)));
    int t3 = (int)fminf(1.f, fmaxf(-1.f, rintf(v.w * ws)));
    g_tw[i] = (unsigned)((t0 & 0xFF) | ((t1 & 0xFF) << 8) | ((t2 & 0xFF) << 16) | (t3 << 24));
}

// ---------------- kernel 4: per-row absmax (at DRAM roofline) ----------------
// Also zeroes g_dot for this row.
__global__ void __launch_bounds__(QT) k_rowmax(const float4* __restrict__ x4) {
    const int row = blockIdx.x;
    const int tid = threadIdx.x;
    if (tid < OUT_FEAT) g_dot[row * OUT_FEAT + tid] = 0;

    const float4* xr = x4 + (size_t)row * IN_G;
    float m = 0.f;
    #pragma unroll 5
    for (int k = 0; k < QK; k++) {
        float4 v = xr[tid + k * QT];
        m = fmaxf(m, fmaxf(fmaxf(fabsf(v.x), fabsf(v.y)),
                           fmaxf(fabsf(v.z), fabsf(v.w))));
    }
    #pragma unroll
    for (int d = 16; d; d >>= 1) m = fmaxf(m, __shfl_down_sync(0xffffffffu, m, d));
    __shared__ float red[QT / 32];
    int warp = tid >> 5, lane = tid & 31;
    if (lane == 0) red[warp] = m;
    __syncthreads();
    if (tid < 32) {
        float v = (tid < QT / 32) ? red[tid] : 0.f;
        #pragma unroll
        for (int d = 16; d; d >>= 1) v = fmaxf(v, __shfl_down_sync(0xffffffffu, v, d));
        if (tid == 0) g_rowscale[row] = 127.f / fmaxf(v, 1e-5f);
    }
}

// Packed f32x2 FMA magic-number quantize: 2 FFMA2 replace 4 FFMA per group.
// The mov.b64 pack/unpack pairs alias register pairs (float4 loads land in
// consecutive regs) so they cost ~0 in SASS. Numerics identical to the
// validated scalar-FMA version (R12 passed with rel_err 5.56e-5).
__device__ __forceinline__ unsigned long long dup_f32(float a) {
    unsigned long long r;
    asm("mov.b64 %0, {%1, %1};" : "=l"(r) : "f"(a));
    return r;
}
__device__ __forceinline__ unsigned quant_pack(float4 v, unsigned long long as2,
                                               unsigned long long mg) {
    unsigned long long xy, zw, r01, r23;
    asm("mov.b64 %0, {%1, %2};" : "=l"(xy) : "f"(v.x), "f"(v.y));
    asm("mov.b64 %0, {%1, %2};" : "=l"(zw) : "f"(v.z), "f"(v.w));
    asm("fma.rn.f32x2 %0, %1, %2, %3;" : "=l"(r01) : "l"(xy), "l"(as2), "l"(mg));
    asm("fma.rn.f32x2 %0, %1, %2, %3;" : "=l"(r23) : "l"(zw), "l"(as2), "l"(mg));
    unsigned f0, f1, f2, f3;
    asm("mov.b64 {%0, %1}, %2;" : "=r"(f0), "=r"(f1) : "l"(r01));
    asm("mov.b64 {%0, %1}, %2;" : "=r"(f2), "=r"(f3) : "l"(r23));
    unsigned p01 = __byte_perm(f0, f1, 0x0040);
    unsigned p23 = __byte_perm(f2, f3, 0x0040);
    return __byte_perm(p01, p23, 0x5410);
}

// ---------------- kernel 5: fused quantize + ternary GEMV, row-TRIPLE batched ----------------
// R9-proven shape: 290 CTAs (2/SM, 24 warps/SM, 84-reg cap). THREE rows per
// iteration: scales first, then 15 streaming LDG.128 (7.5KB in flight/thread),
// each weight LDS serves all three rows. FFMA2 quantize. No syncs in the loop.
__global__ void __launch_bounds__(GT, 2) k_gemv(const float4* __restrict__ x4) {
    extern __shared__ unsigned smem[];
    uint4*    swq = (uint4*)smem;                 // [10][GT] quads (k=0..3)
    unsigned* sws = smem + SWQ_WORDS;             // [10][GT] singles (k=4)

    const int s = blockIdx.x;
    const int rb = blockIdx.y;
    const int tid = threadIdx.x;
    const int lane = tid & 31;
    const int gbase = s * SLICE_G;

    // magic constant as packed f32x2 (hoisted out of the loop)
    unsigned long long mg;
    {
        unsigned mlo = 0x4B400000u;   // 12582912.f = 1.5*2^23
        asm("mov.b64 %0, {%1, %1};" : "=l"(mg) : "r"(mlo));
    }

    // one-time weight staging (L2-resident source)
    #pragma unroll
    for (int o = 0; o < OUT_FEAT; o++) {
        uint4 w;
        w.x = g_tw[o * IN_G + gbase + 0 * GT + tid];
        w.y = g_tw[o * IN_G + gbase + 1 * GT + tid];
        w.z = g_tw[o * IN_G + gbase + 2 * GT + tid];
        w.w = g_tw[o * IN_G + gbase + 3 * GT + tid];
        swq[o * GT + tid] = w;
        sws[o * GT + tid] = g_tw[o * IN_G + gbase + 4 * GT + tid];
    }
    __syncthreads();

    const float4* xb = x4 + gbase + tid;   // thread-fixed base

    int r0 = B_ROWS - 1 - rb;              // descending (harvest rowmax L2 tail)
    while (r0 >= 0) {
        const int r1 = r0 - ROWBLK;
        const int r2 = r0 - 2 * ROWBLK;
        const int r1c = (r1 >= 0) ? r1 : r0;   // tail: dup row (L1-hit), skip its atomic
        const int r2c = (r2 >= 0) ? r2 : r0;

        // scales first, so their latency hides under the x stream
        const unsigned long long as0 = dup_f32(g_rowscale[r0]);
        const unsigned long long as1 = dup_f32(g_rowscale[r1c]);
        const unsigned long long as2 = dup_f32(g_rowscale[r2c]);

        // issue all 15 streaming LDG.128 up-front (7.5KB in flight per thread)
        float4 v0[GPT], v1[GPT], v2[GPT];
        #pragma unroll
        for (int k = 0; k < GPT; k++) v0[k] = __ldcs(xb + (size_t)r0  * IN_G + k * GT);
        #pragma unroll
        for (int k = 0; k < GPT; k++) v1[k] = __ldcs(xb + (size_t)r1c * IN_G + k * GT);
        #pragma unroll
        for (int k = 0; k < GPT; k++) v2[k] = __ldcs(xb + (size_t)r2c * IN_G + k * GT);

        // quantize (v regs die here -> reg pressure drops for dp4a phase)
        unsigned q0[GPT], q1[GPT], q2[GPT];
        #pragma unroll
        for (int k = 0; k < GPT; k++) q0[k] = quant_pack(v0[k], as0, mg);
        #pragma unroll
        for (int k = 0; k < GPT; k++) q1[k] = quant_pack(v1[k], as1, mg);
        #pragma unroll
        for (int k = 0; k < GPT; k++) q2[k] = quant_pack(v2[k], as2, mg);

        // each weight load feeds all THREE rows
        int acc0[OUT_FEAT], acc1[OUT_FEAT], acc2[OUT_FEAT];
        #pragma unroll
        for (int o = 0; o < OUT_FEAT; o++) {
            const uint4 w = swq[o * GT + tid];
            const int ws4 = (int)sws[o * GT + tid];
            int a0 = __dp4a((int)q0[0], (int)w.x, 0);
            int a1 = __dp4a((int)q1[0], (int)w.x, 0);
            int a2 = __dp4a((int)q2[0], (int)w.x, 0);
            a0 = __dp4a((int)q0[1], (int)w.y, a0);
            a1 = __dp4a((int)q1[1], (int)w.y, a1);
            a2 = __dp4a((int)q2[1], (int)w.y, a2);
            a0 = __dp4a((int)q0[2], (int)w.z, a0);
            a1 = __dp4a((int)q1[2], (int)w.z, a1);
            a2 = __dp4a((int)q2[2], (int)w.z, a2);
            a0 = __dp4a((int)q0[3], (int)w.w, a0);
            a1 = __dp4a((int)q1[3], (int)w.w, a1);
            a2 = __dp4a((int)q2[3], (int)w.w, a2);
            acc0[o] = __dp4a((int)q0[4], ws4, a0);
            acc1[o] = __dp4a((int)q1[4], ws4, a1);
            acc2[o] = __dp4a((int)q2[4], ws4, a2);
        }

        // warp reduce + exact integer atomics (order-independent)
        #pragma unroll
        for (int o = 0; o < OUT_FEAT; o++) {
            acc0[o] = __reduce_add_sync(0xffffffffu, acc0[o]);
            acc1[o] = __reduce_add_sync(0xffffffffu, acc1[o]);
            acc2[o] = __reduce_add_sync(0xffffffffu, acc2[o]);
        }
        if (lane == 0) {
            int* d0 = g_dot + r0 * OUT_FEAT;
            #pragma unroll
            for (int o = 0; o < OUT_FEAT; o++) atomicAdd(d0 + o, acc0[o]);
            if (r1 >= 0) {
                int* d1 = g_dot + r1 * OUT_FEAT;
                #pragma unroll
                for (int o = 0; o < OUT_FEAT; o++) atomicAdd(d1 + o, acc1[o]);
            }
            if (r2 >= 0) {
                int* d2 = g_dot + r2 * OUT_FEAT;
                #pragma unroll
                for (int o = 0; o < OUT_FEAT; o++) atomicAdd(d2 + o, acc2[o]);
            }
        }
        r0 -= 3 * ROWBLK;
    }
}

// ---------------- kernel 6: scale, bias, softmax ----------------
__global__ void k_finish(const float* __restrict__ bias, float* __restrict__ out) {
    int row = blockIdx.x * 128 + threadIdx.x;   // grid 8 x 128
    float inv_as = 1.f / g_rowscale[row];
    float coef = inv_as * g_winv;
    const int* dp = g_dot + row * OUT_FEAT;
    float logit[OUT_FEAT];
    float m = -3.4e38f;
    #pragma unroll
    for (int o = 0; o < OUT_FEAT; o++) {
        logit[o] = coef * (float)dp[o] + bias[o];
        m = fmaxf(m, logit[o]);
    }
    float ssum = 0.f;
    #pragma unroll
    for (int o = 0; o < OUT_FEAT; o++) { logit[o] = expf(logit[o] - m); ssum += logit[o]; }
    float inv_s = 1.f / ssum;
    #pragma unroll
    for (int o = 0; o < OUT_FEAT; o++) out[row * OUT_FEAT + o] = logit[o] * inv_s;
}

// ---------------- launch (fork/join: weight chain overlaps rowmax) ----------------
extern "C" void kernel_launch(void* const* d_in, const int* in_sizes, int n_in,
                              void* d_out, int out_size) {
    const float4* x4 = (const float4*)d_in[0];   // [1024,3,160,160] fp32
    const float4* w4 = (const float4*)d_in[1];   // [10,76800] fp32
    const float*  b  = (const float*)d_in[2];    // [10]
    float* out = (float*)d_out;

    static cudaStream_t s_side = nullptr;
    static cudaEvent_t ev_fork = nullptr, ev_join = nullptr;
    static int init_done = 0;
    if (!init_done) {
        cudaStreamCreateWithFlags(&s_side, cudaStreamNonBlocking);
        cudaEventCreateWithFlags(&ev_fork, cudaEventDisableTiming);
        cudaEventCreateWithFlags(&ev_join, cudaEventDisableTiming);
        cudaFuncSetAttribute(k_gemv, cudaFuncAttributeMaxDynamicSharedMemorySize, GEMV_SMEM);
        init_done = 1;
    }

    // fork: weight-prep chain on side stream, concurrent with k_rowmax
    cudaEventRecord(ev_fork, 0);
    cudaStreamWaitEvent(s_side, ev_fork, 0);
    k_wsum<<<WSUM_BLOCKS, WSUM_THREADS, 0, s_side>>>(w4);
    k_wscale<<<1, 128, 0, s_side>>>();
    k_ternary<<<W_G / 256, 256, 0, s_side>>>(w4);
    cudaEventRecord(ev_join, s_side);

    k_rowmax<<<B_ROWS, QT>>>(x4);                 // ~48us, hides the chain

    cudaStreamWaitEvent(0, ev_join, 0);
    dim3 ggrid(NSLICE, ROWBLK);
    k_gemv<<<ggrid, GT, GEMV_SMEM>>>(x4);
    k_finish<<<B_ROWS / 128, 128>>>(b, out);
}